// round 9
// baseline (speedup 1.0000x reference)
#include <cuda_runtime.h>
#include <cstdint>

#define H    768
#define H4   192
#define NT   192            // threads per block (one per float4 column)
#define NB   592            // 148 SMs x 4 blocks, all co-resident by construction
#define RPC  4              // rows per streamed chunk
#define CHB  (RPC * H * 4)  // 12288 bytes per chunk
#define NSTG 3              // pipeline stages
#define NINFU 0xff800000u

// ---------------- scratch (__device__ globals: allocation-free) ----------------
__device__ __align__(16) float g_colmax[H];
__device__ __align__(16) float g_qw[H];
__device__ __align__(16) float g_v[H];
__device__ __align__(16) float g_ep[H];
__device__ float g_pm[NB], g_ps[NB];
__device__ __align__(16) float g_pacc[NB * H];
__device__ unsigned g_cnt = 0, g_gen = 0;

// ---------------- helpers ----------------
__device__ __forceinline__ uint32_t smem_u32(const void* p) {
    uint32_t a;
    asm("{ .reg .u64 t; cvta.to.shared.u64 t, %1; cvt.u32.u64 %0, t; }" : "=r"(a) : "l"(p));
    return a;
}
__device__ __forceinline__ void atomicMaxFloat(float* addr, float val) {
    if (val >= 0.0f) atomicMax((int*)addr, __float_as_int(val));
    else             atomicMin((unsigned int*)addr, __float_as_uint(val));
}
__device__ __forceinline__ float warpReduceSum(float v) {
    #pragma unroll
    for (int o = 16; o; o >>= 1) v += __shfl_xor_sync(0xffffffffu, v, o);
    return v;
}
__device__ __forceinline__ void mbar_wait(uint32_t mbar, int parity) {
    asm volatile(
        "{\n\t.reg .pred P;\n"
        "WAIT_%=:\n\t"
        "mbarrier.try_wait.parity.acquire.cta.shared::cta.b64 P, [%0], %1, 0x989680;\n\t"
        "@P bra DONE_%=;\n\t"
        "bra WAIT_%=;\n"
        "DONE_%=:\n\t}"
        :: "r"(mbar), "r"(parity) : "memory");
}
__device__ __forceinline__ void bulk_issue(uint32_t dst_smem, const void* src, uint32_t mbar) {
    asm volatile("mbarrier.arrive.expect_tx.shared.b64 _, [%0], %1;"
                 :: "r"(mbar), "r"((uint32_t)CHB) : "memory");
    asm volatile(
        "cp.async.bulk.shared::cluster.global.mbarrier::complete_tx::bytes [%0], [%1], %2, [%3];"
        :: "r"(dst_smem), "l"(src), "r"((uint32_t)CHB), "r"(mbar) : "memory");
}
// software grid barrier (all NB blocks resident by construction)
__device__ __forceinline__ void gsync() {
    __syncthreads();
    if (threadIdx.x == 0) {
        __threadfence();
        unsigned gen = atomicAdd(&g_gen, 0u);
        if (atomicAdd(&g_cnt, 1u) == NB - 1u) {
            atomicExch(&g_cnt, 0u);
            __threadfence();
            atomicAdd(&g_gen, 1u);
        } else {
            while (atomicAdd(&g_gen, 0u) == gen) __nanosleep(64);
            __threadfence();
        }
    }
    __syncthreads();
}

// Softmax-merge of NB partials into dst (atomicAdd; dst pre-zeroed). 32 blocks.
__device__ __forceinline__ void merge_phase(float* dst, float* dst2,
                                            int b, int t, float* spf, float* sred) {
    const int chunk = NB / 8;   // 74
    float ninf = __uint_as_float(NINFU);
    float lm = ninf;
    for (int i = t; i < NB; i += NT) lm = fmaxf(lm, g_pm[i]);
    sred[t] = lm;
    __syncthreads();
    if (t == 0) {
        float M = sred[0];
        for (int i = 1; i < NT; i++) M = fmaxf(M, sred[i]);
        sred[NT] = M;
    }
    __syncthreads();
    float M = sred[NT];
    float ls = 0.0f;
    for (int i = t; i < NB; i += NT) ls += __expf(g_pm[i] - M) * g_ps[i];
    sred[t] = ls;
    __syncthreads();
    if (t == 0) {
        float S = 0.0f;
        for (int i = 0; i < NT; i++) S += sred[i];
        sred[NT + 1] = S;
    }
    __syncthreads();
    float S = sred[NT + 1];

    int w0 = (b >> 2) * chunk;
    for (int i = t; i < chunk; i += NT) spf[i] = __expf(g_pm[w0 + i] - M);
    __syncthreads();
    int h = (b & 3) * NT + t;
    float a = 0.0f;
    #pragma unroll 2
    for (int i = 0; i < chunk; i++)
        a += spf[i] * g_pacc[(size_t)(w0 + i) * H + h];
    a /= S;
    atomicAdd(&dst[h], a);
    if (dst2) atomicAdd(&dst2[h], a);
    __syncthreads();
}

// ---------------- the single persistent kernel ----------------
__global__ void __launch_bounds__(NT, 4)
mega_kernel(const float* __restrict__ fact, const float* __restrict__ ep,
            const float* __restrict__ W, float* __restrict__ out, int N, int M) {
    int b = blockIdx.x, t = threadIdx.x;
    int lane = t & 31, wid = t >> 5;
    float ninf = __uint_as_float(NINFU);

    __shared__ __align__(16) float s_buf[NSTG][RPC * H];   // 36 KB stream buffers
    __shared__ float s_sp[RPC][NT];                        // 3 KB
    __shared__ float s_sd[RPC];
    __shared__ float s_sw[RPC + 1];
    __shared__ float s_red[NT + 2];
    __shared__ __align__(8) unsigned long long s_mbar[NSTG];

    uint32_t sb0 = smem_u32(&s_buf[0][0]);
    uint32_t mb0 = smem_u32(&s_mbar[0]);

    if (t == 0) {
        #pragma unroll
        for (int i = 0; i < NSTG; i++)
            asm volatile("mbarrier.init.shared.b64 [%0], 1;" :: "r"(mb0 + 8 * i) : "memory");
        asm volatile("fence.proxy.async.shared::cta;" ::: "memory");
    }
    // pipeline cursors (persist across phases; strict ring order everywhere)
    int cons = 0, iss = 0;
    unsigned ph = 0;

    // ---- P0: init ----
    if (b == 0) {
        for (int i = t; i < H; i += NT) {
            g_colmax[i] = ninf; g_qw[i] = 0.0f; g_ep[i] = 0.0f;
            out[i] = 0.0f; out[i + H] = 0.0f;
        }
    }
    gsync();   // also covers mbarrier-init visibility within the block

    // ---- P1: column max over fact, bulk-copy pipeline ----
    {
        int nch = N / RPC;                      // 8192 chunks of 12 KB
        int next = b, pro = 0;
        while (pro < NSTG && next < nch) {
            if (t == 0) bulk_issue(sb0 + iss * CHB, (const char*)fact + (size_t)next * CHB, mb0 + 8 * iss);
            iss = (iss + 1 == NSTG) ? 0 : iss + 1; next += NB; pro++;
        }
        float4 m4 = make_float4(ninf, ninf, ninf, ninf);
        for (int c = b; c < nch; c += NB) {
            mbar_wait(mb0 + 8 * cons, (ph >> cons) & 1);
            const float4* B = (const float4*)&s_buf[cons][0];
            #pragma unroll
            for (int g = 0; g < RPC; g++) {
                float4 x = B[g * H4 + t];
                m4.x = fmaxf(m4.x, x.x); m4.y = fmaxf(m4.y, x.y);
                m4.z = fmaxf(m4.z, x.z); m4.w = fmaxf(m4.w, x.w);
            }
            __syncthreads();                    // all reads done -> stage reusable
            ph ^= (1u << cons); cons = (cons + 1 == NSTG) ? 0 : cons + 1;
            if (next < nch) {
                if (t == 0) bulk_issue(sb0 + iss * CHB, (const char*)fact + (size_t)next * CHB, mb0 + 8 * iss);
                iss = (iss + 1 == NSTG) ? 0 : iss + 1; next += NB;
            }
        }
        int col = t * 4;
        atomicMaxFloat(&g_colmax[col + 0], m4.x);
        atomicMaxFloat(&g_colmax[col + 1], m4.y);
        atomicMaxFloat(&g_colmax[col + 2], m4.z);
        atomicMaxFloat(&g_colmax[col + 3], m4.w);
    }
    gsync();

    // ---- P2: qw[j] = sum_h colmax[h] * W[h,j]  (96 blocks) ----
    if (b < 96) {
        int j = (b & 3) * NT + t, h0 = (b >> 2) * 32;
        float a = 0.0f;
        #pragma unroll 8
        for (int i = 0; i < 32; i++)
            a += g_colmax[h0 + i] * W[(size_t)(h0 + i) * H + j];
        atomicAdd(&g_qw[j], a);
    }
    gsync();

    // ---- P3 + P6 share this fused streaming routine ----
    // (written twice to keep vsrc selection in device code)
    #define FUSED_PASS(SRC, NCH, VSRC)                                              \
    {                                                                               \
        int nch = (NCH);                                                            \
        int next = b, pro = 0;                                                      \
        while (pro < NSTG && next < nch) {                                          \
            if (t == 0) bulk_issue(sb0 + iss * CHB,                                 \
                                   (const char*)(SRC) + (size_t)next * CHB,         \
                                   mb0 + 8 * iss);                                  \
            iss = (iss + 1 == NSTG) ? 0 : iss + 1; next += NB; pro++;               \
        }                                                                           \
        float4 vc = ((const float4*)(VSRC))[t];                                     \
        float m = ninf, s = 0.0f;                                                   \
        float4 acc = make_float4(0.f, 0.f, 0.f, 0.f);                               \
        for (int c = b; c < nch; c += NB) {                                         \
            mbar_wait(mb0 + 8 * cons, (ph >> cons) & 1);                            \
            const float4* B = (const float4*)&s_buf[cons][0];                       \
            float4 x[RPC];                                                          \
            _Pragma("unroll")                                                       \
            for (int g = 0; g < RPC; g++) x[g] = B[g * H4 + t];                     \
            _Pragma("unroll")                                                       \
            for (int g = 0; g < RPC; g++)                                           \
                s_sp[g][t] = x[g].x * vc.x + x[g].y * vc.y                          \
                           + x[g].z * vc.z + x[g].w * vc.w;                         \
            __syncthreads();            /* buffer reads done -> reusable */         \
            ph ^= (1u << cons); cons = (cons + 1 == NSTG) ? 0 : cons + 1;           \
            if (next < nch) {                                                       \
                if (t == 0) bulk_issue(sb0 + iss * CHB,                             \
                                       (const char*)(SRC) + (size_t)next * CHB,     \
                                       mb0 + 8 * iss);                              \
                iss = (iss + 1 == NSTG) ? 0 : iss + 1; next += NB;                  \
            }                                                                       \
            if (wid < RPC) {                                                        \
                float v = 0.0f;                                                     \
                _Pragma("unroll")                                                   \
                for (int k = 0; k < 6; k++) v += s_sp[wid][lane + 32 * k];          \
                v = warpReduceSum(v);                                               \
                if (lane == 0) s_sd[wid] = v;                                       \
            }                                                                       \
            __syncthreads();                                                        \
            if (t == 0) {                                                           \
                float mn = m;                                                       \
                _Pragma("unroll")                                                   \
                for (int g = 0; g < RPC; g++) mn = fmaxf(mn, s_sd[g]);              \
                float sc = __expf(m - mn);                                          \
                float ls = s * sc;                                                  \
                _Pragma("unroll")                                                   \
                for (int g = 0; g < RPC; g++) {                                     \
                    float w = __expf(s_sd[g] - mn); s_sw[g] = w; ls += w;           \
                }                                                                   \
                s_sw[RPC] = sc; s = ls; m = mn;                                     \
            }                                                                       \
            __syncthreads();                                                        \
            float sc = s_sw[RPC];                                                   \
            acc.x *= sc; acc.y *= sc; acc.z *= sc; acc.w *= sc;                     \
            _Pragma("unroll")                                                       \
            for (int g = 0; g < RPC; g++) {                                         \
                float w = s_sw[g];                                                  \
                acc.x += w * x[g].x; acc.y += w * x[g].y;                           \
                acc.z += w * x[g].z; acc.w += w * x[g].w;                           \
            }                                                                       \
        }                                                                           \
        if (t == 0) { g_pm[b] = m; g_ps[b] = s; }                                   \
        ((float4*)g_pacc)[b * H4 + t] = acc;                                        \
    }

    // ---- P3: elements_p fused pass (all blocks, 1024 chunks) ----
    FUSED_PASS(ep, M / RPC, g_qw)
    gsync();

    // ---- P4: merge ep partials -> g_ep and out[768:] ----
    if (b < 32) merge_phase(g_ep, out + H, b, t, &s_sp[0][0], s_red);
    gsync();

    // ---- P5: v[row] = W[row,:] . ep_  (128 blocks x 6 warps) ----
    if (b < 128) {
        int row = b * 6 + wid;
        const float4* r = (const float4*)(W + (size_t)row * H);
        float p = 0.0f;
        #pragma unroll
        for (int k = 0; k < 6; k++) {
            float4 a = r[lane + 32 * k];
            float4 e = ((const float4*)g_ep)[lane + 32 * k];
            p += a.x * e.x + a.y * e.y + a.z * e.z + a.w * e.w;
        }
        p = warpReduceSum(p);
        if (lane == 0) g_v[row] = p;
    }
    gsync();

    // ---- P6: fact fused pass (all blocks, 8192 chunks) ----
    FUSED_PASS(fact, N / RPC, g_v)
    gsync();

    // ---- P7: merge fact partials -> out[0:768] ----
    if (b < 32) merge_phase(out, nullptr, b, t, &s_sp[0][0], s_red);
}

// ---------------- launch ----------------
extern "C" void kernel_launch(void* const* d_in, const int* in_sizes, int n_in,
                              void* d_out, int out_size) {
    const float *fact = nullptr, *ep = nullptr, *W = nullptr;
    int N = 0, M = 0;
    for (int i = 0; i < n_in; i++) {
        long long sz = in_sizes[i];
        if (sz == (long long)H * H)           W    = (const float*)d_in[i];
        else if (sz == (long long)4096 * H) { ep   = (const float*)d_in[i]; M = 4096; }
        else                                { fact = (const float*)d_in[i]; N = (int)(sz / H); }
    }
    mega_kernel<<<NB, NT>>>(fact, ep, W, (float*)d_out, N, M);
}

// round 10
// speedup vs baseline: 1.2028x; 1.2028x over previous
#include <cuda_runtime.h>
#include <cstdint>

#define H    768
#define H4   192
#define NT   192            // threads per block (one per float4 column)
#define NB   740            // 148 SMs x 5 blocks, all co-resident by construction
#define RPC  4              // rows per streamed chunk
#define CHB  (RPC * H * 4)  // 12288 bytes per chunk
#define NSTG 3              // pipeline stages
#define NINFU 0xff800000u

// ---------------- scratch (__device__ globals: allocation-free) ----------------
__device__ __align__(16) float g_colmax[H];
__device__ __align__(16) float g_qw[H];
__device__ __align__(16) float g_v[H];
__device__ __align__(16) float g_ep[H];
__device__ float g_pm[NB], g_ps[NB];
__device__ __align__(16) float g_pacc[NB * H];   // 2.27 MB
__device__ unsigned g_cnt = 0, g_gen = 0;

// ---------------- helpers ----------------
__device__ __forceinline__ uint32_t smem_u32(const void* p) {
    uint32_t a;
    asm("{ .reg .u64 t; cvta.to.shared.u64 t, %1; cvt.u32.u64 %0, t; }" : "=r"(a) : "l"(p));
    return a;
}
__device__ __forceinline__ void atomicMaxFloat(float* addr, float val) {
    if (val >= 0.0f) atomicMax((int*)addr, __float_as_int(val));
    else             atomicMin((unsigned int*)addr, __float_as_uint(val));
}
__device__ __forceinline__ float warpReduceSum(float v) {
    #pragma unroll
    for (int o = 16; o; o >>= 1) v += __shfl_xor_sync(0xffffffffu, v, o);
    return v;
}
__device__ __forceinline__ float warpReduceMax(float v) {
    #pragma unroll
    for (int o = 16; o; o >>= 1) v = fmaxf(v, __shfl_xor_sync(0xffffffffu, v, o));
    return v;
}
__device__ __forceinline__ void mbar_wait(uint32_t mbar, int parity) {
    asm volatile(
        "{\n\t.reg .pred P;\n"
        "WAIT_%=:\n\t"
        "mbarrier.try_wait.parity.acquire.cta.shared::cta.b64 P, [%0], %1, 0x989680;\n\t"
        "@P bra DONE_%=;\n\t"
        "bra WAIT_%=;\n"
        "DONE_%=:\n\t}"
        :: "r"(mbar), "r"(parity) : "memory");
}
__device__ __forceinline__ void bulk_issue(uint32_t dst_smem, const void* src, uint32_t mbar) {
    asm volatile("mbarrier.arrive.expect_tx.shared.b64 _, [%0], %1;"
                 :: "r"(mbar), "r"((uint32_t)CHB) : "memory");
    asm volatile(
        "cp.async.bulk.shared::cluster.global.mbarrier::complete_tx::bytes [%0], [%1], %2, [%3];"
        :: "r"(dst_smem), "l"(src), "r"((uint32_t)CHB), "r"(mbar) : "memory");
}
// grid barrier: arrivals via one atomic each; POLLING VIA PLAIN VOLATILE LOADS
// (no atomic-pipe contention). Valid: all NB blocks resident by construction.
__device__ __forceinline__ void gsync() {
    __syncthreads();
    if (threadIdx.x == 0) {
        __threadfence();
        volatile unsigned* vg = &g_gen;
        unsigned gen = *vg;                       // read BEFORE own arrival
        if (atomicAdd(&g_cnt, 1u) == NB - 1u) {
            atomicExch(&g_cnt, 0u);
            __threadfence();
            atomicAdd(&g_gen, 1u);                // release
        } else {
            while (*vg == gen) __nanosleep(128);  // plain L2 read poll
            __threadfence();                      // acquire
        }
    }
    __syncthreads();
}

// ---------------- the single persistent kernel ----------------
__global__ void __launch_bounds__(NT, 5)
mega_kernel(const float* __restrict__ fact, const float* __restrict__ ep,
            const float* __restrict__ W, float* __restrict__ out, int N, int M) {
    int b = blockIdx.x, t = threadIdx.x;
    int lane = t & 31, wid = t >> 5;
    float ninf = __uint_as_float(NINFU);

    __shared__ __align__(16) float s_buf[NSTG][RPC * H];   // 36 KB
    __shared__ float s_sp[RPC][NT];                        // 3 KB
    __shared__ float s_sd[RPC];
    __shared__ float s_red[8];
    __shared__ __align__(8) unsigned long long s_mbar[NSTG];

    uint32_t sb0 = smem_u32(&s_buf[0][0]);
    uint32_t mb0 = smem_u32(&s_mbar[0]);

    if (t == 0) {
        #pragma unroll
        for (int i = 0; i < NSTG; i++)
            asm volatile("mbarrier.init.shared.b64 [%0], 1;" :: "r"(mb0 + 8 * i) : "memory");
        asm volatile("fence.proxy.async.shared::cta;" ::: "memory");
    }
    int cons = 0, iss = 0;     // ring cursors persist across phases
    unsigned ph = 0;

    // ---- P0: init ----
    if (b == 0) {
        for (int i = t; i < H; i += NT) {
            g_colmax[i] = ninf; g_qw[i] = 0.0f; g_ep[i] = 0.0f;
            out[i] = 0.0f; out[i + H] = 0.0f;
        }
    }
    gsync();   // B1 (also covers local mbarrier init)

    // ---- P1: column max over fact, TMA pipeline ----
    {
        int nch = N / RPC;
        int next = b, pro = 0;
        while (pro < NSTG && next < nch) {
            if (t == 0) bulk_issue(sb0 + iss * CHB, (const char*)fact + (size_t)next * CHB, mb0 + 8 * iss);
            iss = (iss + 1 == NSTG) ? 0 : iss + 1; next += NB; pro++;
        }
        float4 m4 = make_float4(ninf, ninf, ninf, ninf);
        for (int c = b; c < nch; c += NB) {
            mbar_wait(mb0 + 8 * cons, (ph >> cons) & 1);
            const float4* B = (const float4*)&s_buf[cons][0];
            #pragma unroll
            for (int g = 0; g < RPC; g++) {
                float4 x = B[g * H4 + t];
                m4.x = fmaxf(m4.x, x.x); m4.y = fmaxf(m4.y, x.y);
                m4.z = fmaxf(m4.z, x.z); m4.w = fmaxf(m4.w, x.w);
            }
            __syncthreads();
            ph ^= (1u << cons); cons = (cons + 1 == NSTG) ? 0 : cons + 1;
            if (next < nch) {
                if (t == 0) bulk_issue(sb0 + iss * CHB, (const char*)fact + (size_t)next * CHB, mb0 + 8 * iss);
                iss = (iss + 1 == NSTG) ? 0 : iss + 1; next += NB;
            }
        }
        int col = t * 4;
        atomicMaxFloat(&g_colmax[col + 0], m4.x);
        atomicMaxFloat(&g_colmax[col + 1], m4.y);
        atomicMaxFloat(&g_colmax[col + 2], m4.z);
        atomicMaxFloat(&g_colmax[col + 3], m4.w);
    }
    gsync();   // B2

    // ---- P2: qw[j] = sum_h colmax[h] * W[h,j]  (96 blocks) ----
    if (b < 96) {
        int j = (b & 3) * NT + t, h0 = (b >> 2) * 32;
        float a = 0.0f;
        #pragma unroll 8
        for (int i = 0; i < 32; i++)
            a += g_colmax[h0 + i] * W[(size_t)(h0 + i) * H + j];
        atomicAdd(&g_qw[j], a);
    }
    gsync();   // B3

    // Fused streaming pass: 2 syncs per chunk, exps on ALL threads (no serial section)
    #define FUSED_PASS(SRC, NCH, VSRC)                                              \
    {                                                                               \
        int nch = (NCH);                                                            \
        int next = b, pro = 0;                                                      \
        while (pro < NSTG && next < nch) {                                          \
            if (t == 0) bulk_issue(sb0 + iss * CHB,                                 \
                                   (const char*)(SRC) + (size_t)next * CHB,         \
                                   mb0 + 8 * iss);                                  \
            iss = (iss + 1 == NSTG) ? 0 : iss + 1; next += NB; pro++;               \
        }                                                                           \
        float4 vc = ((const float4*)(VSRC))[t];                                     \
        float m = ninf, s = 0.0f;                                                   \
        float4 acc = make_float4(0.f, 0.f, 0.f, 0.f);                               \
        for (int c = b; c < nch; c += NB) {                                         \
            mbar_wait(mb0 + 8 * cons, (ph >> cons) & 1);                            \
            const float4* B = (const float4*)&s_buf[cons][0];                       \
            float4 x[RPC];                                                          \
            _Pragma("unroll")                                                       \
            for (int g = 0; g < RPC; g++) x[g] = B[g * H4 + t];                     \
            _Pragma("unroll")                                                       \
            for (int g = 0; g < RPC; g++)                                           \
                s_sp[g][t] = x[g].x * vc.x + x[g].y * vc.y                          \
                           + x[g].z * vc.z + x[g].w * vc.w;                         \
            __syncthreads();           /* sp ready; buffer reads done */            \
            ph ^= (1u << cons); cons = (cons + 1 == NSTG) ? 0 : cons + 1;           \
            if (next < nch) {                                                       \
                if (t == 0) bulk_issue(sb0 + iss * CHB,                             \
                                       (const char*)(SRC) + (size_t)next * CHB,     \
                                       mb0 + 8 * iss);                              \
                iss = (iss + 1 == NSTG) ? 0 : iss + 1; next += NB;                  \
            }                                                                       \
            if (wid < RPC) {                                                        \
                float v = 0.0f;                                                     \
                _Pragma("unroll")                                                   \
                for (int k = 0; k < 6; k++) v += s_sp[wid][lane + 32 * k];          \
                v = warpReduceSum(v);                                               \
                if (lane == 0) s_sd[wid] = v;                                       \
            }                                                                       \
            __syncthreads();           /* sd ready */                               \
            float d0 = s_sd[0], d1 = s_sd[1], d2 = s_sd[2], d3 = s_sd[3];           \
            float mn = fmaxf(fmaxf(fmaxf(d0, d1), fmaxf(d2, d3)), m);               \
            float sc = __expf(m - mn);                                              \
            float w0 = __expf(d0 - mn), w1 = __expf(d1 - mn);                       \
            float w2 = __expf(d2 - mn), w3 = __expf(d3 - mn);                       \
            s = s * sc + w0 + w1 + w2 + w3;                                         \
            m = mn;                                                                 \
            acc.x = acc.x * sc + w0 * x[0].x + w1 * x[1].x + w2 * x[2].x + w3 * x[3].x; \
            acc.y = acc.y * sc + w0 * x[0].y + w1 * x[1].y + w2 * x[2].y + w3 * x[3].y; \
            acc.z = acc.z * sc + w0 * x[0].z + w1 * x[1].z + w2 * x[2].z + w3 * x[3].z; \
            acc.w = acc.w * sc + w0 * x[0].w + w1 * x[1].w + w2 * x[2].w + w3 * x[3].w; \
        }                                                                           \
        if (t == 0) { g_pm[b] = m; g_ps[b] = s; }                                   \
        ((float4*)g_pacc)[b * H4 + t] = acc;                                        \
    }

    // ---- P3: elements_p fused pass ----
    FUSED_PASS(ep, M / RPC, g_qw)
    gsync();   // B4

    // Merge: ALL NB blocks; each handles 4 partials x 192 columns; M,S redundant.
    #define MERGE_PHASE(DST, DST2)                                                  \
    {                                                                               \
        float lm = ninf;                                                            \
        _Pragma("unroll")                                                           \
        for (int q = 0; q < 4; q++) {                                               \
            int i = t + q * NT;                                                     \
            if (i < NB) lm = fmaxf(lm, g_pm[i]);                                    \
        }                                                                           \
        lm = warpReduceMax(lm);                                                     \
        if (lane == 0) s_red[wid] = lm;                                             \
        __syncthreads();                                                            \
        if (t == 0) {                                                               \
            float Mx = s_red[0];                                                    \
            _Pragma("unroll")                                                       \
            for (int i = 1; i < 6; i++) Mx = fmaxf(Mx, s_red[i]);                   \
            s_red[6] = Mx;                                                          \
        }                                                                           \
        __syncthreads();                                                            \
        float Mx = s_red[6];                                                        \
        float lsum = 0.0f;                                                          \
        _Pragma("unroll")                                                           \
        for (int q = 0; q < 4; q++) {                                               \
            int i = t + q * NT;                                                     \
            if (i < NB) lsum += __expf(g_pm[i] - Mx) * g_ps[i];                     \
        }                                                                           \
        lsum = warpReduceSum(lsum);                                                 \
        if (lane == 0) s_red[wid] = lsum;                                           \
        __syncthreads();                                                            \
        if (t == 0) {                                                               \
            float S = 0.0f;                                                         \
            _Pragma("unroll")                                                       \
            for (int i = 0; i < 6; i++) S += s_red[i];                              \
            s_red[7] = S;                                                           \
        }                                                                           \
        __syncthreads();                                                            \
        float S = s_red[7];                                                         \
        int w0i = (b >> 2) * 4;                                                     \
        int h = (b & 3) * NT + t;                                                   \
        float a = 0.0f;                                                             \
        _Pragma("unroll")                                                           \
        for (int i = 0; i < 4; i++)                                                 \
            a += __expf(g_pm[w0i + i] - Mx) * g_pacc[(size_t)(w0i + i) * H + h];    \
        a /= S;                                                                     \
        atomicAdd(&(DST)[h], a);                                                    \
        if (DST2) atomicAdd(&((float*)(DST2))[h], a);                               \
        __syncthreads();                                                            \
    }

    // ---- P4: merge ep partials -> g_ep and out[768:] ----
    MERGE_PHASE(g_ep, out + H)
    gsync();   // B5

    // ---- P5: v[row] = W[row,:] . ep_  (128 blocks x 6 warps) ----
    if (b < 128) {
        int row = b * 6 + wid;
        const float4* r = (const float4*)(W + (size_t)row * H);
        float p = 0.0f;
        #pragma unroll
        for (int k = 0; k < 6; k++) {
            float4 a4 = r[lane + 32 * k];
            float4 e4 = ((const float4*)g_ep)[lane + 32 * k];
            p += a4.x * e4.x + a4.y * e4.y + a4.z * e4.z + a4.w * e4.w;
        }
        p = warpReduceSum(p);
        if (lane == 0) g_v[row] = p;
    }
    gsync();   // B6

    // ---- P6: fact fused pass ----
    FUSED_PASS(fact, N / RPC, g_v)
    gsync();   // B7

    // ---- P7: merge fact partials -> out[0:768] ----
    MERGE_PHASE(out, (float*)nullptr)
}

// ---------------- launch ----------------
extern "C" void kernel_launch(void* const* d_in, const int* in_sizes, int n_in,
                              void* d_out, int out_size) {
    const float *fact = nullptr, *ep = nullptr, *W = nullptr;
    int N = 0, M = 0;
    for (int i = 0; i < n_in; i++) {
        long long sz = in_sizes[i];
        if (sz == (long long)H * H)           W    = (const float*)d_in[i];
        else if (sz == (long long)4096 * H) { ep   = (const float*)d_in[i]; M = 4096; }
        else                                { fact = (const float*)d_in[i]; N = (int)(sz / H); }
    }
    mega_kernel<<<NB, NT>>>(fact, ep, W, (float*)d_out, N, M);
}